// round 11
// baseline (speedup 1.0000x reference)
#include <cuda_runtime.h>

#define BB 16      // batches
#define NP 2048    // points per batch
#define NC 64      // feature channels
#define NS 512     // fps samples
#define NK 24      // knn k
#define NKNNBLK (BB * 64)   // 1024 knn blocks

// scratch (no allocation allowed)
__device__ int    g_fidx[BB * NS];
__device__ int    g_gidx[BB * NS * NK];
__device__ double g_sum[BB];
__device__ double g_sq[BB];
__device__ float  g_inv[BB];
__device__ int    g_cnt = 0;

__device__ __forceinline__ unsigned redux_max_u32(unsigned v) {
    unsigned r;
    asm volatile("redux.sync.max.u32 %0, %1, 0xffffffff;" : "=r"(r) : "r"(v));
    return r;
}
__device__ __forceinline__ unsigned redux_min_u32(unsigned v) {
    unsigned r;
    asm volatile("redux.sync.min.u32 %0, %1, 0xffffffff;" : "=r"(r) : "r"(v));
    return r;
}

// Blackwell packed f32x2 ops (elementwise rn -> bit-identical to scalar rn)
#define PACK_F32X2(out, lo, hi) \
    asm("mov.b64 %0, {%1, %2};" : "=l"(out) : "r"(lo), "r"(hi))
#define UNPACK_F32X2(lo, hi, in) \
    asm("mov.b64 {%0, %1}, %2;" : "=r"(lo), "=r"(hi) : "l"(in))
#define ADD_F32X2(out, a, b) \
    asm("add.rn.f32x2 %0, %1, %2;" : "=l"(out) : "l"(a), "l"(b))
#define MUL_F32X2(out, a, b) \
    asm("mul.rn.f32x2 %0, %1, %2;" : "=l"(out) : "l"(a), "l"(b))

// shared-memory union: fps role and knn role never coexist in one block
union SmemU {
    struct {
        float4 sp4[NP];                       // 32 KB
        unsigned long long sw[2][8];
    } fps;
    struct {
        float4 sp4[NP];                       // 32 KB
        int    sidx[8][NK];
        int    sqi[8];
        double ws[8], wq[8];
        int    s_last;
    } knn;
};

// ---------------------------------------------------------------------------
// init: g_fidx = -1 (spin sentinel) for ALL BB*NS entries, zero accumulators.
// 32 blocks x 256 threads = 8192 threads == BB*NS exactly.
// ---------------------------------------------------------------------------
__global__ void init_kernel() {
    const int t = blockIdx.x * 256 + threadIdx.x;
    if (t < BB * NS) g_fidx[t] = -1;
    if (t < BB) { g_sum[t] = 0.0; g_sq[t] = 0.0; }
}

// ---------------------------------------------------------------------------
// FPS body: identical algorithm to the verified bit-exact kernel; the g_fidx
// store is volatile (it doubles as the readiness flag for spinning knn
// blocks — the index word IS the payload, sentinel -1).
// ---------------------------------------------------------------------------
__device__ __forceinline__
void fps_body(SmemU& sm, int b,
              const float* __restrict__ pts,
              float* __restrict__ out_idx, float* __restrict__ out_sp) {
    const int t = threadIdx.x;
    const float* P = pts + b * NP * 3;
    volatile int* fidx = (volatile int*)(g_fidx + b * NS);

    unsigned long long px2[4], py2[4], pz2[4];
    float m[8];
    #pragma unroll
    for (int k = 0; k < 4; ++k) {
        const int ilo = t + (2*k)   * 256;
        const int ihi = t + (2*k+1) * 256;
        const float xl = P[3*ilo], yl = P[3*ilo+1], zl = P[3*ilo+2];
        const float xh = P[3*ihi], yh = P[3*ihi+1], zh = P[3*ihi+2];
        sm.fps.sp4[ilo] = make_float4(xl, yl, zl, 0.f);
        sm.fps.sp4[ihi] = make_float4(xh, yh, zh, 0.f);
        PACK_F32X2(px2[k], __float_as_uint(xl), __float_as_uint(xh));
        PACK_F32X2(py2[k], __float_as_uint(yl), __float_as_uint(yh));
        PACK_F32X2(pz2[k], __float_as_uint(zl), __float_as_uint(zh));
        m[2*k] = 1e10f; m[2*k+1] = 1e10f;
    }
    __syncthreads();

    int cur = 0;
    const int wid = t >> 5, lane = t & 31;
    const bool emit_idx = (out_idx != nullptr);
    const bool emit_sp  = (out_sp  != nullptr);

    for (int it = 0; it < NS; ++it) {
        const float4 c = sm.fps.sp4[cur];
        if (t == 0) {
            fidx[it] = cur;                           // volatile: flag + payload
            if (emit_idx) out_idx[b * NS + it] = (float)cur;
            if (emit_sp) {
                float* o = out_sp + (b * NS + it) * 3;
                o[0] = c.x; o[1] = c.y; o[2] = c.z;
            }
        }
        const unsigned nx = __float_as_uint(-c.x);
        const unsigned ny = __float_as_uint(-c.y);
        const unsigned nz = __float_as_uint(-c.z);
        unsigned long long ncx2, ncy2, ncz2;
        PACK_F32X2(ncx2, nx, nx);
        PACK_F32X2(ncy2, ny, ny);
        PACK_F32X2(ncz2, nz, nz);

        unsigned f[8];
        #pragma unroll
        for (int k = 0; k < 4; ++k) {
            unsigned long long dx2, dy2, dz2, xx, yy, zz, ss, dd;
            ADD_F32X2(dx2, px2[k], ncx2);     // px - cx (exact)
            ADD_F32X2(dy2, py2[k], ncy2);
            ADD_F32X2(dz2, pz2[k], ncz2);
            MUL_F32X2(xx, dx2, dx2);
            MUL_F32X2(yy, dy2, dy2);
            MUL_F32X2(zz, dz2, dz2);
            ADD_F32X2(ss, xx, yy);            // (dx^2 + dy^2)
            ADD_F32X2(dd, ss, zz);            // ... + dz^2
            unsigned dlo, dhi;
            UNPACK_F32X2(dlo, dhi, dd);
            m[2*k]   = fminf(m[2*k],   __uint_as_float(dlo));
            m[2*k+1] = fminf(m[2*k+1], __uint_as_float(dhi));
            f[2*k]   = __float_as_uint(m[2*k]);    // nonneg: bit order == float order
            f[2*k+1] = __float_as_uint(m[2*k+1]);
        }
        unsigned bv = f[0];
        #pragma unroll
        for (int j = 1; j < 8; ++j) bv = max(bv, f[j]);
        const unsigned wm = redux_max_u32(bv);
        unsigned cand = 0xffffffffu;
        #pragma unroll
        for (int j = 7; j >= 0; --j)          // descending overwrite -> smallest idx
            if (f[j] == wm) cand = (unsigned)(t + j * 256);
        const unsigned wi = redux_min_u32(cand);
        if (lane == 0)
            sm.fps.sw[it & 1][wid] = ((unsigned long long)wm << 32) | (unsigned)(~wi);
        __syncthreads();
        unsigned long long best = sm.fps.sw[it & 1][0];
        #pragma unroll
        for (int w2 = 1; w2 < 8; ++w2) best = max(best, sm.fps.sw[it & 1][w2]);
        cur = (int)(~(unsigned)best);
    }
}

// ---------------------------------------------------------------------------
// kNN body: identical selection to verified kernel; query index obtained by
// spinning on g_fidx[b,s] (sentinel -1) so knn overlaps fps.
// Fused per-batch stats; the last knn block computes g_inv and resets g_cnt.
// ---------------------------------------------------------------------------
__device__ __forceinline__
void knn_body(SmemU& sm, int kblk,
              const float* __restrict__ pts,
              const float* __restrict__ feat) {
    const int b    = kblk >> 6;
    const int sgrp = kblk & 63;
    const int t = threadIdx.x, lane = t & 31, w = t >> 5;
    const int s = sgrp * 8 + w;
    const float* P = pts + b * NP * 3;

    #pragma unroll
    for (int j = 0; j < 8; ++j) {
        const int i = t + j * 256;
        const float x = P[3*i], y = P[3*i+1], z = P[3*i+2];
        const float n2 = __fadd_rn(__fadd_rn(__fmul_rn(x,x), __fmul_rn(y,y)), __fmul_rn(z,z));
        sm.knn.sp4[i] = make_float4(x, y, z, n2);
    }
    __syncthreads();

    // spin until fps has produced this sample's index (word is payload+flag)
    int qi;
    for (;;) {
        qi = *((volatile int*)(g_fidx + b * NS + s));
        if (qi >= 0) break;
        __nanosleep(128);
    }

    const float4 qp = sm.knn.sp4[qi];
    const float sx = qp.x, sy = qp.y, sz = qp.z;
    const float d2 = qp.w;
    if (lane == 0) sm.knn.sqi[w] = qi;

    auto dist_key = [&](int n) -> unsigned {
        const float4 p = sm.knn.sp4[n];
        const float d3 = __fmaf_rn(sz, p.z, __fmaf_rn(sy, p.y, __fmul_rn(sx, p.x)));
        const float d  = __fsub_rn(__fadd_rn(p.w, d2), __fmul_rn(2.0f, d3));
        const unsigned bits = __float_as_uint(d);
        return (bits & 0x80000000u) ? ~bits : (bits | 0x80000000u);
    };

    unsigned long long removed = 0ull;
    unsigned long long gm[8];
    unsigned long long lb = ~0ull;
    #pragma unroll
    for (int g = 0; g < 8; ++g) {
        unsigned long long v = ~0ull;
        #pragma unroll
        for (int j = 0; j < 8; ++j) {
            const int i = g * 8 + j;
            const int n = i * 32 + lane;
            v = min(v, ((unsigned long long)dist_key(n) << 32) | (unsigned)n);
        }
        gm[g] = v;
        lb = min(lb, v);
    }

    int* gout = g_gidx + (b * NS + s) * NK;
    for (int r = 0; r < NK; ++r) {
        const unsigned lbk = (unsigned)(lb >> 32);
        const unsigned wk  = redux_min_u32(lbk);
        const unsigned cand = (lbk == wk) ? (unsigned)lb : 0xffffffffu;  // low = n
        const unsigned wi   = redux_min_u32(cand);
        if (lane == 0) { gout[r] = (int)wi; sm.knn.sidx[w][r] = (int)wi; }
        if (r == NK - 1) break;
        if ((wi & 31u) == (unsigned)lane) {   // owner rebuilds its group
            const int i = (int)(wi >> 5);
            removed |= 1ull << i;
            const int g = i >> 3;
            unsigned long long v = ~0ull;
            #pragma unroll
            for (int j = 0; j < 8; ++j) {
                const int ii = g * 8 + j;
                const int n = ii * 32 + lane;
                const unsigned key = ((removed >> ii) & 1ull) ? 0xffffffffu : dist_key(n);
                v = min(v, ((unsigned long long)key << 32) | (unsigned)n);
            }
            #pragma unroll
            for (int gg = 0; gg < 8; ++gg) if (gg == g) gm[gg] = v;
            unsigned long long nlb = ~0ull;
            #pragma unroll
            for (int g2 = 0; g2 < 8; ++g2) nlb = min(nlb, gm[g2]);
            lb = nlb;
        }
    }
    __syncthreads();   // sidx/sqi complete for all warps

    // fused stats: this block's 8 queries x 24 neighbors x 16 float4
    const float4* F4 = (const float4*)(feat + b * NP * NC);
    double s_acc = 0.0, q_acc = 0.0;
    #pragma unroll
    for (int u = 0; u < 12; ++u) {
        const int e  = t + u * 256;        // 0..3071
        const int c4 = e & 15;
        const int wj = e >> 4;             // 0..191
        const int ww = wj / NK;
        const int j  = wj % NK;
        const float4 a  = F4[sm.knn.sidx[ww][j] * 16 + c4];
        const float4 mm = F4[sm.knn.sqi[ww] * 16 + c4];
        const float vx = a.x - mm.x, vy = a.y - mm.y, vz = a.z - mm.z, vw = a.w - mm.w;
        s_acc += (double)vx + (double)vy + (double)vz + (double)vw;
        q_acc += (double)vx * vx + (double)vy * vy + (double)vz * vz + (double)vw * vw;
    }
    #pragma unroll
    for (int off = 16; off > 0; off >>= 1) {
        s_acc += __shfl_down_sync(0xffffffffu, s_acc, off);
        q_acc += __shfl_down_sync(0xffffffffu, q_acc, off);
    }
    if (lane == 0) { sm.knn.ws[w] = s_acc; sm.knn.wq[w] = q_acc; }
    __syncthreads();
    if (t == 0) {
        double ts = sm.knn.ws[0], tq = sm.knn.wq[0];
        #pragma unroll
        for (int w2 = 1; w2 < 8; ++w2) { ts += sm.knn.ws[w2]; tq += sm.knn.wq[w2]; }
        atomicAdd(&g_sum[b], ts);
        atomicAdd(&g_sq[b], tq);
        __threadfence();
        const int old = atomicAdd(&g_cnt, 1);
        sm.knn.s_last = (old == NKNNBLK - 1) ? 1 : 0;
    }
    __syncthreads();
    if (sm.knn.s_last) {                   // last knn block: 1/(std+eps)
        if (t < BB) {
            const double rN  = 1.0 / (double)(NS * NK * NC);
            const double rN1 = 1.0 / (double)(NS * NK * NC - 1);
            const double sum = g_sum[t], sq = g_sq[t];
            double var = (sq - sum * sum * rN) * rN1;
            if (var < 0.0) var = 0.0;
            g_inv[t] = 1.0f / ((float)sqrt(var) + 1e-5f);
        }
        if (t == 0) g_cnt = 0;             // reset for graph determinism
    }
}

// ---------------------------------------------------------------------------
// fused kernel: blocks 0..15 = FPS (one per batch); blocks 16.. = kNN+stats
// ---------------------------------------------------------------------------
__global__ __launch_bounds__(256)
void fused_kernel(const float* __restrict__ pts,
                  const float* __restrict__ feat,
                  float* __restrict__ out_idx,
                  float* __restrict__ out_sp) {
    __shared__ SmemU sm;
    if (blockIdx.x < BB) {
        fps_body(sm, blockIdx.x, pts, out_idx, out_sp);
    } else {
        knn_body(sm, blockIdx.x - BB, pts, feat);
    }
}

// ---------------------------------------------------------------------------
// finalize (pure float, streaming stores):
//   out[..,0:64] = alpha*(centered*inv)+beta ; out[..,64:128] = mean
// ---------------------------------------------------------------------------
__global__ __launch_bounds__(256)
void finalize_kernel(const float* __restrict__ feat,
                     const float* __restrict__ alpha,
                     const float* __restrict__ beta,
                     float* __restrict__ out) {
    const int TOT4 = BB * NS * NK * (NC / 4);
    const int gid = blockIdx.x * 256 + threadIdx.x;
    if (gid >= TOT4) return;
    const int c4  = gid & 15;
    const int sj  = gid >> 4;               // b*NS*NK + s*NK + j
    const int b   = sj / (NS * NK);
    const int rem = sj % (NS * NK);
    const int s   = rem / NK;

    const float* F = feat + b * NP * NC;
    const int gi = g_gidx[sj];
    const int fi = g_fidx[b * NS + s];

    const float4 mean = *(const float4*)(F + fi * NC + c4 * 4);
    const float4 gv   = *(const float4*)(F + gi * NC + c4 * 4);
    const float4 al   = *(const float4*)(alpha + c4 * 4);
    const float4 be   = *(const float4*)(beta  + c4 * 4);
    const float inv   = g_inv[b];

    float4 gf;
    gf.x = al.x * ((gv.x - mean.x) * inv) + be.x;
    gf.y = al.y * ((gv.y - mean.y) * inv) + be.y;
    gf.z = al.z * ((gv.z - mean.z) * inv) + be.z;
    gf.w = al.w * ((gv.w - mean.w) * inv) + be.w;

    float* o = out + sj * 128;
    __stcs((float4*)(o + c4 * 4), gf);
    __stcs((float4*)(o + 64 + c4 * 4), mean);
}

// ---------------------------------------------------------------------------
extern "C" void kernel_launch(void* const* d_in, const int* in_sizes, int n_in,
                              void* d_out, int out_size) {
    const float* pts   = (const float*)d_in[0];   // 16x2048x3
    const float* feat  = (const float*)d_in[1];   // 16x2048x64
    const float* alpha = (const float*)d_in[2];   // 64
    const float* beta  = (const float*)d_in[3];   // 64
    float* out = (float*)d_out;

    const int SZ_IDX = BB * NS;
    const int SZ_SP  = BB * NS * 3;
    const int SZ_OF  = BB * NS * NK * 2 * NC;

    float* out_idx = nullptr;
    float* out_sp  = nullptr;
    float* out_f   = out;
    if (out_size >= SZ_IDX + SZ_SP + SZ_OF) {
        out_idx = out;
        out_sp  = out + SZ_IDX;
        out_f   = out + SZ_IDX + SZ_SP;
    }

    init_kernel<<<32, 256>>>();           // ALL g_fidx = -1, sums = 0

    fused_kernel<<<BB + NKNNBLK, 256>>>(pts, feat, out_idx, out_sp);

    const int TOT4 = BB * NS * NK * (NC / 4);
    finalize_kernel<<<(TOT4 + 255) / 256, 256>>>(feat, alpha, beta, out_f);
}